// round 7
// baseline (speedup 1.0000x reference)
#include <cuda_runtime.h>
#include <cstdint>
#include <math.h>

// Problem constants
#define Bz 4
#define Sz 2048
#define Dz 1024
#define Hz 16
#define HDz 64
#define D3z 3072
#define Mz (Bz * Sz)

// Scratch (device globals: allocation-free per harness rules)
// K-permuted layout: within each 8-element K-block, order [e0,e4,e1,e5,e2,e6,e3,e7]
__device__ float g_qkv[(size_t)Mz * D3z];   // [8192, 3072] (unpermuted)
__device__ float g_attn[(size_t)Mz * Dz];   // [8192, 1024] (tf32, K-permuted)
__device__ float g_x[(size_t)Mz * Dz];      // tf32, K-permuted
__device__ float g_wq[(size_t)D3z * Dz];    // tf32, K-permuted
__device__ float g_wp[(size_t)Dz * Dz];     // tf32, K-permuted

// ---------------------------------------------------------------------------
// Helpers
// ---------------------------------------------------------------------------
__device__ __forceinline__ uint32_t smem_u32(const void* p) {
    uint32_t a;
    asm("{ .reg .u64 t; cvta.to.shared.u64 t, %1; cvt.u32.u64 %0, t; }"
        : "=r"(a) : "l"(p));
    return a;
}

__device__ __forceinline__ uint32_t f2tf32(float x) {
    uint32_t r;
    asm("cvt.rna.tf32.f32 %0, %1;" : "=r"(r) : "f"(x));
    return r;
}

#define CP_ASYNC16(dst, src) \
    asm volatile("cp.async.cg.shared.global [%0], [%1], 16;" \
        :: "r"((uint32_t)(dst)), "l"(src) : "memory")
#define CP_COMMIT() asm volatile("cp.async.commit_group;" ::: "memory")
#define CP_WAIT1() asm volatile("cp.async.wait_group 1;" ::: "memory")
#define CP_WAIT0() asm volatile("cp.async.wait_group 0;" ::: "memory")

// m16n8k8 tf32 MMA (sm_80+, valid at compute_103)
__device__ __forceinline__ void mma_tf32(
    float& d0, float& d1, float& d2, float& d3,
    uint32_t a0, uint32_t a1, uint32_t a2, uint32_t a3,
    uint32_t b0, uint32_t b1)
{
    asm volatile(
        "mma.sync.aligned.m16n8k8.row.col.f32.tf32.tf32.f32 "
        "{%0,%1,%2,%3}, {%4,%5,%6,%7}, {%8,%9}, {%0,%1,%2,%3};"
        : "+f"(d0), "+f"(d1), "+f"(d2), "+f"(d3)
        : "r"(a0), "r"(a1), "r"(a2), "r"(a3), "r"(b0), "r"(b1));
}

// ---------------------------------------------------------------------------
// Fused tf32 rounding + K-permute pass over x, w_qkv, w_proj.
// Each thread handles one 8-element K-block: out = [e0,e4,e1,e5,e2,e6,e3,e7].
// ---------------------------------------------------------------------------
#define N8_X  (Mz * Dz / 8)
#define N8_WQ (D3z * Dz / 8)
#define N8_WP (Dz * Dz / 8)

__global__ __launch_bounds__(256) void cvt_all_kernel(
    const float* __restrict__ x,  float* __restrict__ xo,
    const float* __restrict__ wq, float* __restrict__ wqo,
    const float* __restrict__ wp, float* __restrict__ wpo)
{
    int i = blockIdx.x * blockDim.x + threadIdx.x;
    const float4* src;
    uint4* dst;
    int j;
    if (i < N8_X)                { src = (const float4*)x;  dst = (uint4*)xo;  j = i; }
    else if (i < N8_X + N8_WQ)   { src = (const float4*)wq; dst = (uint4*)wqo; j = i - N8_X; }
    else if (i < N8_X + N8_WQ + N8_WP)
                                 { src = (const float4*)wp; dst = (uint4*)wpo; j = i - N8_X - N8_WQ; }
    else return;
    float4 v0 = src[2 * j];
    float4 v1 = src[2 * j + 1];
    uint4 o0, o1;
    o0.x = f2tf32(v0.x); o0.y = f2tf32(v1.x);
    o0.z = f2tf32(v0.y); o0.w = f2tf32(v1.y);
    o1.x = f2tf32(v0.z); o1.y = f2tf32(v1.z);
    o1.z = f2tf32(v0.w); o1.w = f2tf32(v1.w);
    dst[2 * j]     = o0;
    dst[2 * j + 1] = o1;
}

// ---------------------------------------------------------------------------
// tf32 mma.sync NT GEMM on K-permuted inputs.
// 128x128 CTA, BK=32, 8 warps (4Mx2N). 2-stage cp.async, AST=40
// (conflict-free LDS.64 fragment loads). 2 CTAs/SM.
// ---------------------------------------------------------------------------
#define STAGES 2
#define BK 32
#define AST 40
#define STAGE_FLOATS (128 * AST * 2)            // 10240
#define GEMM_SMEM (STAGES * STAGE_FLOATS * 4)   // 81920 bytes

__global__ __launch_bounds__(256, 2)
void gemm_mma_kernel(const float* __restrict__ A, const float* __restrict__ B,
                     float* __restrict__ C, int M, int N, int K)
{
    extern __shared__ float smf[];
    uint32_t sb = smem_u32(smf);
    const int tid = threadIdx.x;
    const int wid = tid >> 5;
    const int l   = tid & 31;
    const int g   = l >> 2;
    const int tg  = l & 3;
    const int wm  = wid >> 1;
    const int wn  = wid & 1;
    const int m0  = blockIdx.y * 128;
    const int n0  = blockIdx.x * 128;
    const int nchunk = K / BK;

    auto issue = [&](int c, int s) {
        uint32_t sA = sb + (uint32_t)s * STAGE_FLOATS * 4;
        uint32_t sB = sA + 128u * AST * 4;
        const float* Ab = A + (size_t)m0 * K + c * BK;
        const float* Bb = B + (size_t)n0 * K + c * BK;
        #pragma unroll
        for (int i = 0; i < 4; i++) {
            int idx = tid + 256 * i;
            int row = idx >> 3;
            int c4  = idx & 7;
            uint32_t so = (uint32_t)(row * AST + c4 * 4) * 4;
            CP_ASYNC16(sA + so, Ab + (size_t)row * K + c4 * 4);
            CP_ASYNC16(sB + so, Bb + (size_t)row * K + c4 * 4);
        }
        CP_COMMIT();
    };

    float acc[2][8][4];
    #pragma unroll
    for (int mt = 0; mt < 2; mt++)
        #pragma unroll
        for (int nt = 0; nt < 8; nt++)
            #pragma unroll
            for (int q = 0; q < 4; q++) acc[mt][nt][q] = 0.f;

    issue(0, 0);

    const int abase = (wm * 32 + g) * AST + 2 * tg;       // +mt*16*AST +s4*8
    const int bbase = (wn * 64 + g) * AST + 2 * tg;       // +nt*8*AST +s4*8

    for (int c = 0; c < nchunk; c++) {
        __syncthreads();   // all warps done reading stage (c+1)&1 (chunk c-1)
        if (c + 1 < nchunk) { issue(c + 1, (c + 1) & 1); CP_WAIT1(); }
        else                { CP_WAIT0(); }
        __syncthreads();

        const uint32_t* Au = (const uint32_t*)(smf + (size_t)(c & 1) * STAGE_FLOATS);
        const uint32_t* Bu = Au + 128 * AST;

        #pragma unroll
        for (int s4 = 0; s4 < 4; s4++) {
            uint32_t a[2][4];
            #pragma unroll
            for (int mt = 0; mt < 2; mt++) {
                int base = abase + mt * 16 * AST + s4 * 8;
                uint2 lo = *(const uint2*)&Au[base];             // row g:   (k, k+4)
                uint2 hi = *(const uint2*)&Au[base + 8 * AST];   // row g+8: (k, k+4)
                a[mt][0] = lo.x; a[mt][2] = lo.y;
                a[mt][1] = hi.x; a[mt][3] = hi.y;
            }
            uint32_t b[8][2];
            #pragma unroll
            for (int nt = 0; nt < 8; nt++) {
                uint2 bv = *(const uint2*)&Bu[bbase + nt * 8 * AST + s4 * 8];
                b[nt][0] = bv.x; b[nt][1] = bv.y;
            }
            #pragma unroll
            for (int mt = 0; mt < 2; mt++)
                #pragma unroll
                for (int nt = 0; nt < 8; nt++)
                    mma_tf32(acc[mt][nt][0], acc[mt][nt][1],
                             acc[mt][nt][2], acc[mt][nt][3],
                             a[mt][0], a[mt][1], a[mt][2], a[mt][3],
                             b[nt][0], b[nt][1]);
        }
    }

    #pragma unroll
    for (int mt = 0; mt < 2; mt++) {
        int r = m0 + wm * 32 + mt * 16 + g;
        #pragma unroll
        for (int nt = 0; nt < 8; nt++) {
            int cc = n0 + wn * 64 + nt * 8 + tg * 2;
            *(float2*)&C[(size_t)r * N + cc] =
                make_float2(acc[mt][nt][0], acc[mt][nt][1]);
            *(float2*)&C[(size_t)(r + 8) * N + cc] =
                make_float2(acc[mt][nt][2], acc[mt][nt][3]);
        }
    }
}

// ---------------------------------------------------------------------------
// Tensor-core flash attention (tf32 mma.sync).
// q-tile 128 x (head, batch); 256 threads / 8 warps; warp owns 16 q-rows.
// K/V tiles of 64 keys amortized over 128 q-rows. Epilogue writes K-permuted
// tf32 values (feeds proj GEMM directly).
// ---------------------------------------------------------------------------
#define KST 68
#define VST 72
#define PST 68
#define QTILE 128
#define ATT_SMEM ((64 * KST + 64 * VST + QTILE * PST) * 4)   // 70656 bytes

__global__ __launch_bounds__(256, 2) void attn_mma_kernel(
    const float* __restrict__ qkv, float* __restrict__ out)
{
    extern __shared__ float sm[];
    uint32_t* Ku = (uint32_t*)sm;
    uint32_t* Vu = Ku + 64 * KST;
    uint32_t* Pu = Vu + 64 * VST;

    const int tid = threadIdx.x;
    const int w  = tid >> 5;
    const int l  = tid & 31;
    const int g  = l >> 2;
    const int tg = l & 3;
    const int qt = blockIdx.x;
    const int h  = blockIdx.y;
    const int b  = blockIdx.z;
    const int q0 = qt * QTILE;
    const size_t bh = (size_t)b * Sz * D3z + (size_t)h * HDz;
    const float NEG_INF = -__int_as_float(0x7f800000);

    // Stage Q (scaled by 1/8, tf32-rounded) into Pu [128 rows]
    for (int idx = tid; idx < QTILE * 16; idx += 256) {
        int r = idx >> 4, c4 = (idx & 15) << 2;
        float4 v = *(const float4*)(qkv + bh + (size_t)(q0 + r) * D3z + c4);
        uint4 o4;
        o4.x = f2tf32(v.x * 0.125f); o4.y = f2tf32(v.y * 0.125f);
        o4.z = f2tf32(v.z * 0.125f); o4.w = f2tf32(v.w * 0.125f);
        *(uint4*)&Pu[r * PST + c4] = o4;
    }
    __syncthreads();

    uint32_t qa[8][4];
    const int pr0 = (w * 16 + g) * PST;
    const int pr1 = pr0 + 8 * PST;
    #pragma unroll
    for (int kk = 0; kk < 8; kk++) {
        qa[kk][0] = Pu[pr0 + kk * 8 + tg];
        qa[kk][1] = Pu[pr1 + kk * 8 + tg];
        qa[kk][2] = Pu[pr0 + kk * 8 + tg + 4];
        qa[kk][3] = Pu[pr1 + kk * 8 + tg + 4];
    }

    float o[8][4];
    #pragma unroll
    for (int nt = 0; nt < 8; nt++)
        #pragma unroll
        for (int q = 0; q < 4; q++) o[nt][q] = 0.f;
    float m0 = NEG_INF, m1 = NEG_INF, l0 = 0.f, l1 = 0.f;

    const int nkt = 2 * qt + 2;   // 64-key tiles covering (qt+1)*128 keys
    for (int kt = 0; kt < nkt; kt++) {
        const int k0 = kt * 64;
        __syncthreads();
        for (int idx = tid; idx < 1024; idx += 256) {
            int r = idx >> 4, c4 = (idx & 15) << 2;
            const float* p = qkv + bh + (size_t)(k0 + r) * D3z + Dz + c4;
            float4 kv = *(const float4*)p;
            float4 vv = *(const float4*)(p + Dz);
            uint4 k4, v4;
            k4.x = f2tf32(kv.x); k4.y = f2tf32(kv.y);
            k4.z = f2tf32(kv.z); k4.w = f2tf32(kv.w);
            v4.x = f2tf32(vv.x); v4.y = f2tf32(vv.y);
            v4.z = f2tf32(vv.z); v4.w = f2tf32(vv.w);
            *(uint4*)&Ku[r * KST + c4] = k4;
            *(uint4*)&Vu[r * VST + c4] = v4;
        }
        __syncthreads();

        const bool active = (k0 <= q0 + w * 16 + 15);   // some row sees this tile
        if (!active) continue;

        float s[8][4];
        #pragma unroll
        for (int nt = 0; nt < 8; nt++)
            #pragma unroll
            for (int q = 0; q < 4; q++) s[nt][q] = 0.f;

        #pragma unroll
        for (int kk = 0; kk < 8; kk++) {
            #pragma unroll
            for (int nt = 0; nt < 8; nt++) {
                int kb = (nt * 8 + g) * KST + kk * 8 + tg;
                uint32_t b0 = Ku[kb];
                uint32_t b1 = Ku[kb + 4];
                mma_tf32(s[nt][0], s[nt][1], s[nt][2], s[nt][3],
                         qa[kk][0], qa[kk][1], qa[kk][2], qa[kk][3], b0, b1);
            }
        }

        if (k0 + 63 > q0 + w * 16) {   // diagonal zone for this warp
            int gi0 = q0 + w * 16 + g, gi1 = gi0 + 8;
            #pragma unroll
            for (int nt = 0; nt < 8; nt++) {
                int gj = k0 + nt * 8 + 2 * tg;
                if (gj     > gi0) s[nt][0] = NEG_INF;
                if (gj + 1 > gi0) s[nt][1] = NEG_INF;
                if (gj     > gi1) s[nt][2] = NEG_INF;
                if (gj + 1 > gi1) s[nt][3] = NEG_INF;
            }
        }

        float r0 = NEG_INF, r1 = NEG_INF;
        #pragma unroll
        for (int nt = 0; nt < 8; nt++) {
            r0 = fmaxf(r0, fmaxf(s[nt][0], s[nt][1]));
            r1 = fmaxf(r1, fmaxf(s[nt][2], s[nt][3]));
        }
        r0 = fmaxf(r0, __shfl_xor_sync(0xffffffffu, r0, 1));
        r0 = fmaxf(r0, __shfl_xor_sync(0xffffffffu, r0, 2));
        r1 = fmaxf(r1, __shfl_xor_sync(0xffffffffu, r1, 1));
        r1 = fmaxf(r1, __shfl_xor_sync(0xffffffffu, r1, 2));

        float nm0 = fmaxf(m0, r0), nm1 = fmaxf(m1, r1);
        float a0 = __expf(m0 - nm0), a1 = __expf(m1 - nm1);
        float sum0 = 0.f, sum1 = 0.f;
        #pragma unroll
        for (int nt = 0; nt < 8; nt++) {
            s[nt][0] = __expf(s[nt][0] - nm0);
            s[nt][1] = __expf(s[nt][1] - nm0);
            s[nt][2] = __expf(s[nt][2] - nm1);
            s[nt][3] = __expf(s[nt][3] - nm1);
            sum0 += s[nt][0] + s[nt][1];
            sum1 += s[nt][2] + s[nt][3];
        }
        sum0 += __shfl_xor_sync(0xffffffffu, sum0, 1);
        sum0 += __shfl_xor_sync(0xffffffffu, sum0, 2);
        sum1 += __shfl_xor_sync(0xffffffffu, sum1, 1);
        sum1 += __shfl_xor_sync(0xffffffffu, sum1, 2);
        m0 = nm0; m1 = nm1;
        l0 = l0 * a0 + sum0;
        l1 = l1 * a1 + sum1;

        #pragma unroll
        for (int nt = 0; nt < 8; nt++) {
            o[nt][0] *= a0; o[nt][1] *= a0;
            o[nt][2] *= a1; o[nt][3] *= a1;
        }

        // P round-trip through warp-private SMEM rows
        #pragma unroll
        for (int nt = 0; nt < 8; nt++) {
            int c0 = nt * 8 + 2 * tg;
            Pu[pr0 + c0]     = f2tf32(s[nt][0]);
            Pu[pr0 + c0 + 1] = f2tf32(s[nt][1]);
            Pu[pr1 + c0]     = f2tf32(s[nt][2]);
            Pu[pr1 + c0 + 1] = f2tf32(s[nt][3]);
        }
        __syncwarp();

        #pragma unroll
        for (int kk = 0; kk < 8; kk++) {
            uint32_t pa0 = Pu[pr0 + kk * 8 + tg];
            uint32_t pa1 = Pu[pr1 + kk * 8 + tg];
            uint32_t pa2 = Pu[pr0 + kk * 8 + tg + 4];
            uint32_t pa3 = Pu[pr1 + kk * 8 + tg + 4];
            #pragma unroll
            for (int nt = 0; nt < 8; nt++) {
                uint32_t b0 = Vu[(kk * 8 + tg) * VST + nt * 8 + g];
                uint32_t b1 = Vu[(kk * 8 + tg + 4) * VST + nt * 8 + g];
                mma_tf32(o[nt][0], o[nt][1], o[nt][2], o[nt][3],
                         pa0, pa1, pa2, pa3, b0, b1);
            }
        }
    }

    // Epilogue: scale by 1/l, tf32-round, write K-PERMUTED for the proj GEMM.
    // Column c within its 8-block goes to position 2*(c&3) + (c>>2).
    float i0v = 1.f / l0, i1v = 1.f / l1;
    const int c0l = 2 * tg, c1l = 2 * tg + 1;
    const int p0 = 2 * (c0l & 3) + (c0l >> 2);
    const int p1 = 2 * (c1l & 3) + (c1l >> 2);
    uint32_t* o0p = (uint32_t*)(out + (size_t)(b * Sz + q0 + w * 16 + g) * Dz + h * HDz);
    uint32_t* o1p = o0p + (size_t)8 * Dz;
    #pragma unroll
    for (int nt = 0; nt < 8; nt++) {
        o0p[nt * 8 + p0] = f2tf32(o[nt][0] * i0v);
        o0p[nt * 8 + p1] = f2tf32(o[nt][1] * i0v);
        o1p[nt * 8 + p0] = f2tf32(o[nt][2] * i1v);
        o1p[nt * 8 + p1] = f2tf32(o[nt][3] * i1v);
    }
}

// ---------------------------------------------------------------------------
extern "C" void kernel_launch(void* const* d_in, const int* in_sizes, int n_in,
                              void* d_out, int out_size)
{
    const float* x      = (const float*)d_in[0];
    const float* w_qkv  = (const float*)d_in[1];
    const float* w_proj = (const float*)d_in[2];
    float* out = (float*)d_out;

    void *qkvp, *attnp, *xp, *wqp, *wpp;
    cudaGetSymbolAddress(&qkvp, g_qkv);
    cudaGetSymbolAddress(&attnp, g_attn);
    cudaGetSymbolAddress(&xp, g_x);
    cudaGetSymbolAddress(&wqp, g_wq);
    cudaGetSymbolAddress(&wpp, g_wp);

    cudaFuncSetAttribute(attn_mma_kernel,
                         cudaFuncAttributeMaxDynamicSharedMemorySize, ATT_SMEM);
    cudaFuncSetAttribute(gemm_mma_kernel,
                         cudaFuncAttributeMaxDynamicSharedMemorySize, GEMM_SMEM);

    const int M = Mz;

    // 0) tf32-round + K-permute all GEMM inputs in one pass
    {
        int total = N8_X + N8_WQ + N8_WP;
        cvt_all_kernel<<<(total + 255) / 256, 256>>>(
            x, (float*)xp, w_qkv, (float*)wqp, w_proj, (float*)wpp);
    }

    // 1) QKV projection (tensor cores): [8192,1024] x [3072,1024]^T
    gemm_mma_kernel<<<dim3(D3z / 128, M / 128), 256, GEMM_SMEM>>>(
        (const float*)xp, (const float*)wqp, (float*)qkvp, M, D3z, Dz);

    // 2) Causal flash attention (tensor cores) -> g_attn (tf32, K-permuted)
    attn_mma_kernel<<<dim3(Sz / QTILE, Hz, Bz), 256, ATT_SMEM>>>(
        (const float*)qkvp, (float*)attnp);

    // 3) Output projection (tensor cores): [8192,1024] x [1024,1024]^T
    gemm_mma_kernel<<<dim3(Dz / 128, M / 128), 256, GEMM_SMEM>>>(
        (const float*)attnp, (const float*)wpp, out, M, Dz, Dz);
}

// round 8
// speedup vs baseline: 1.0223x; 1.0223x over previous
#include <cuda_runtime.h>
#include <cstdint>
#include <math.h>

// Problem constants
#define Bz 4
#define Sz 2048
#define Dz 1024
#define Hz 16
#define HDz 64
#define D3z 3072
#define Mz (Bz * Sz)

// Scratch (device globals: allocation-free per harness rules)
// K-permuted layout: within each 8-element K-block, order [e0,e4,e1,e5,e2,e6,e3,e7]
__device__ float g_qkv[(size_t)Mz * D3z];   // [8192, 3072] (unpermuted)
__device__ float g_attn[(size_t)Mz * Dz];   // [8192, 1024] (tf32, K-permuted)
__device__ float g_x[(size_t)Mz * Dz];      // tf32, K-permuted
__device__ float g_wq[(size_t)D3z * Dz];    // tf32, K-permuted
__device__ float g_wp[(size_t)Dz * Dz];     // tf32, K-permuted

// ---------------------------------------------------------------------------
// Helpers
// ---------------------------------------------------------------------------
__device__ __forceinline__ uint32_t smem_u32(const void* p) {
    uint32_t a;
    asm("{ .reg .u64 t; cvta.to.shared.u64 t, %1; cvt.u32.u64 %0, t; }"
        : "=r"(a) : "l"(p));
    return a;
}

__device__ __forceinline__ uint32_t f2tf32(float x) {
    uint32_t r;
    asm("cvt.rna.tf32.f32 %0, %1;" : "=r"(r) : "f"(x));
    return r;
}

#define CP_ASYNC16(dst, src) \
    asm volatile("cp.async.cg.shared.global [%0], [%1], 16;" \
        :: "r"((uint32_t)(dst)), "l"(src) : "memory")
#define CP_COMMIT() asm volatile("cp.async.commit_group;" ::: "memory")
#define CP_WAIT1() asm volatile("cp.async.wait_group 1;" ::: "memory")
#define CP_WAIT0() asm volatile("cp.async.wait_group 0;" ::: "memory")

// m16n8k8 tf32 MMA (sm_80+, valid at compute_103)
__device__ __forceinline__ void mma_tf32(
    float& d0, float& d1, float& d2, float& d3,
    uint32_t a0, uint32_t a1, uint32_t a2, uint32_t a3,
    uint32_t b0, uint32_t b1)
{
    asm volatile(
        "mma.sync.aligned.m16n8k8.row.col.f32.tf32.tf32.f32 "
        "{%0,%1,%2,%3}, {%4,%5,%6,%7}, {%8,%9}, {%0,%1,%2,%3};"
        : "+f"(d0), "+f"(d1), "+f"(d2), "+f"(d3)
        : "r"(a0), "r"(a1), "r"(a2), "r"(a3), "r"(b0), "r"(b1));
}

// ---------------------------------------------------------------------------
// Fused tf32 rounding + K-permute pass over x, w_qkv, w_proj.
// Each thread handles one 8-element K-block: out = [e0,e4,e1,e5,e2,e6,e3,e7].
// ---------------------------------------------------------------------------
#define N8_X  (Mz * Dz / 8)
#define N8_WQ (D3z * Dz / 8)
#define N8_WP (Dz * Dz / 8)

__global__ __launch_bounds__(256) void cvt_all_kernel(
    const float* __restrict__ x,  float* __restrict__ xo,
    const float* __restrict__ wq, float* __restrict__ wqo,
    const float* __restrict__ wp, float* __restrict__ wpo)
{
    int i = blockIdx.x * blockDim.x + threadIdx.x;
    const float4* src;
    uint4* dst;
    int j;
    if (i < N8_X)                { src = (const float4*)x;  dst = (uint4*)xo;  j = i; }
    else if (i < N8_X + N8_WQ)   { src = (const float4*)wq; dst = (uint4*)wqo; j = i - N8_X; }
    else if (i < N8_X + N8_WQ + N8_WP)
                                 { src = (const float4*)wp; dst = (uint4*)wpo; j = i - N8_X - N8_WQ; }
    else return;
    float4 v0 = src[2 * j];
    float4 v1 = src[2 * j + 1];
    uint4 o0, o1;
    o0.x = f2tf32(v0.x); o0.y = f2tf32(v1.x);
    o0.z = f2tf32(v0.y); o0.w = f2tf32(v1.y);
    o1.x = f2tf32(v0.z); o1.y = f2tf32(v1.z);
    o1.z = f2tf32(v0.w); o1.w = f2tf32(v1.w);
    dst[2 * j]     = o0;
    dst[2 * j + 1] = o1;
}

// ---------------------------------------------------------------------------
// tf32 mma.sync NT GEMM on K-permuted inputs.
// 128x128 CTA, BK=32, 8 warps (4Mx2N). 3-stage cp.async + fully
// double-buffered register fragments (no reg cap: occupancy 1).
// ---------------------------------------------------------------------------
#define STAGES 3
#define BK 32
#define AST 40
#define STAGE_FLOATS (128 * AST * 2)            // 10240
#define GEMM_SMEM (STAGES * STAGE_FLOATS * 4)   // 122880 bytes

__global__ __launch_bounds__(256, 1)
void gemm_mma_kernel(const float* __restrict__ A, const float* __restrict__ B,
                     float* __restrict__ C, int M, int N, int K)
{
    extern __shared__ float smf[];
    uint32_t sb = smem_u32(smf);
    const int tid = threadIdx.x;
    const int wid = tid >> 5;
    const int l   = tid & 31;
    const int g   = l >> 2;
    const int tg  = l & 3;
    const int wm  = wid >> 1;
    const int wn  = wid & 1;
    const int m0  = blockIdx.y * 128;
    const int n0  = blockIdx.x * 128;
    const int nchunk = K / BK;

    auto issue = [&](int c, int s) {
        uint32_t sA = sb + (uint32_t)s * STAGE_FLOATS * 4;
        uint32_t sB = sA + 128u * AST * 4;
        const float* Ab = A + (size_t)m0 * K + c * BK;
        const float* Bb = B + (size_t)n0 * K + c * BK;
        #pragma unroll
        for (int i = 0; i < 4; i++) {
            int idx = tid + 256 * i;
            int row = idx >> 3;
            int c4  = idx & 7;
            uint32_t so = (uint32_t)(row * AST + c4 * 4) * 4;
            CP_ASYNC16(sA + so, Ab + (size_t)row * K + c4 * 4);
            CP_ASYNC16(sB + so, Bb + (size_t)row * K + c4 * 4);
        }
        CP_COMMIT();
    };

    float acc[2][8][4];
    #pragma unroll
    for (int mt = 0; mt < 2; mt++)
        #pragma unroll
        for (int nt = 0; nt < 8; nt++)
            #pragma unroll
            for (int q = 0; q < 4; q++) acc[mt][nt][q] = 0.f;

    issue(0, 0);
    issue(1, 1);

    const int abase = (wm * 32 + g) * AST + 2 * tg;   // +mt*16*AST +s4*8
    const int bbase = (wn * 64 + g) * AST + 2 * tg;   // +nt*8*AST  +s4*8

    uint32_t af[2][2][4];   // [buf][mt][frag]
    uint32_t bf[2][8][2];   // [buf][nt][frag]

    for (int c = 0; c < nchunk; c++) {
        if (c == nchunk - 1) { CP_WAIT0(); } else { CP_WAIT1(); }
        __syncthreads();     // also: all warps finished reading stage (c-1)%3

        const uint32_t* Au = (const uint32_t*)(smf + (size_t)(c % STAGES) * STAGE_FLOATS);
        const uint32_t* Bu = Au + 128 * AST;

        // Prefetch k-step 0 fragments into buffer 0
        #pragma unroll
        for (int mt = 0; mt < 2; mt++) {
            int base = abase + mt * 16 * AST;
            uint2 lo = *(const uint2*)&Au[base];
            uint2 hi = *(const uint2*)&Au[base + 8 * AST];
            af[0][mt][0] = lo.x; af[0][mt][2] = lo.y;
            af[0][mt][1] = hi.x; af[0][mt][3] = hi.y;
        }
        #pragma unroll
        for (int nt = 0; nt < 8; nt++) {
            uint2 bv = *(const uint2*)&Bu[bbase + nt * 8 * AST];
            bf[0][nt][0] = bv.x; bf[0][nt][1] = bv.y;
        }

        // Issue chunk c+2 while fragment loads are in flight
        int cn = c + 2;
        if (cn < nchunk) issue(cn, cn % STAGES);

        #pragma unroll
        for (int s4 = 0; s4 < 4; s4++) {
            const int cur = s4 & 1, nxt = cur ^ 1;
            if (s4 < 3) {
                #pragma unroll
                for (int mt = 0; mt < 2; mt++) {
                    int base = abase + mt * 16 * AST + (s4 + 1) * 8;
                    uint2 lo = *(const uint2*)&Au[base];
                    uint2 hi = *(const uint2*)&Au[base + 8 * AST];
                    af[nxt][mt][0] = lo.x; af[nxt][mt][2] = lo.y;
                    af[nxt][mt][1] = hi.x; af[nxt][mt][3] = hi.y;
                }
                #pragma unroll
                for (int nt = 0; nt < 8; nt++) {
                    uint2 bv = *(const uint2*)&Bu[bbase + nt * 8 * AST + (s4 + 1) * 8];
                    bf[nxt][nt][0] = bv.x; bf[nxt][nt][1] = bv.y;
                }
            }
            #pragma unroll
            for (int mt = 0; mt < 2; mt++)
                #pragma unroll
                for (int nt = 0; nt < 8; nt++)
                    mma_tf32(acc[mt][nt][0], acc[mt][nt][1],
                             acc[mt][nt][2], acc[mt][nt][3],
                             af[cur][mt][0], af[cur][mt][1],
                             af[cur][mt][2], af[cur][mt][3],
                             bf[cur][nt][0], bf[cur][nt][1]);
        }
    }

    #pragma unroll
    for (int mt = 0; mt < 2; mt++) {
        int r = m0 + wm * 32 + mt * 16 + g;
        #pragma unroll
        for (int nt = 0; nt < 8; nt++) {
            int cc = n0 + wn * 64 + nt * 8 + tg * 2;
            *(float2*)&C[(size_t)r * N + cc] =
                make_float2(acc[mt][nt][0], acc[mt][nt][1]);
            *(float2*)&C[(size_t)(r + 8) * N + cc] =
                make_float2(acc[mt][nt][2], acc[mt][nt][3]);
        }
    }
}

// ---------------------------------------------------------------------------
// Tensor-core flash attention (tf32 mma.sync). QTILE=64, 4 CTAs/SM (R6-proven).
// Longest CTAs (high qt) scheduled first. Epilogue writes K-permuted tf32.
// ---------------------------------------------------------------------------
#define KST 68
#define VST 72
#define PST 68
#define ATT_SMEM ((64 * KST + 64 * VST + 64 * PST) * 4)   // 53248 bytes

__global__ __launch_bounds__(128, 4) void attn_mma_kernel(
    const float* __restrict__ qkv, float* __restrict__ out)
{
    extern __shared__ float sm[];
    uint32_t* Ku = (uint32_t*)sm;
    uint32_t* Vu = Ku + 64 * KST;
    uint32_t* Pu = Vu + 64 * VST;

    const int tid = threadIdx.x;
    const int w  = tid >> 5;
    const int l  = tid & 31;
    const int g  = l >> 2;
    const int tg = l & 3;
    const int qt = gridDim.x - 1 - blockIdx.x;   // longest work first
    const int h  = blockIdx.y;
    const int b  = blockIdx.z;
    const int q0 = qt * 64;
    const size_t bh = (size_t)b * Sz * D3z + (size_t)h * HDz;
    const float NEG_INF = -__int_as_float(0x7f800000);

    // Stage Q (scaled by 1/8, tf32-rounded) into Pu
    for (int idx = tid; idx < 1024; idx += 128) {
        int r = idx >> 4, c4 = (idx & 15) << 2;
        float4 v = *(const float4*)(qkv + bh + (size_t)(q0 + r) * D3z + c4);
        uint4 o4;
        o4.x = f2tf32(v.x * 0.125f); o4.y = f2tf32(v.y * 0.125f);
        o4.z = f2tf32(v.z * 0.125f); o4.w = f2tf32(v.w * 0.125f);
        *(uint4*)&Pu[r * PST + c4] = o4;
    }
    __syncthreads();

    uint32_t qa[8][4];
    const int pr0 = (w * 16 + g) * PST;
    const int pr1 = pr0 + 8 * PST;
    #pragma unroll
    for (int kk = 0; kk < 8; kk++) {
        qa[kk][0] = Pu[pr0 + kk * 8 + tg];
        qa[kk][1] = Pu[pr1 + kk * 8 + tg];
        qa[kk][2] = Pu[pr0 + kk * 8 + tg + 4];
        qa[kk][3] = Pu[pr1 + kk * 8 + tg + 4];
    }

    float o[8][4];
    #pragma unroll
    for (int nt = 0; nt < 8; nt++)
        #pragma unroll
        for (int q = 0; q < 4; q++) o[nt][q] = 0.f;
    float m0 = NEG_INF, m1 = NEG_INF, l0 = 0.f, l1 = 0.f;

    for (int kt = 0; kt <= qt; kt++) {
        const int k0 = kt * 64;
        __syncthreads();
        for (int idx = tid; idx < 1024; idx += 128) {
            int r = idx >> 4, c4 = (idx & 15) << 2;
            const float* p = qkv + bh + (size_t)(k0 + r) * D3z + Dz + c4;
            float4 kv = *(const float4*)p;
            float4 vv = *(const float4*)(p + Dz);
            uint4 k4, v4;
            k4.x = f2tf32(kv.x); k4.y = f2tf32(kv.y);
            k4.z = f2tf32(kv.z); k4.w = f2tf32(kv.w);
            v4.x = f2tf32(vv.x); v4.y = f2tf32(vv.y);
            v4.z = f2tf32(vv.z); v4.w = f2tf32(vv.w);
            *(uint4*)&Ku[r * KST + c4] = k4;
            *(uint4*)&Vu[r * VST + c4] = v4;
        }
        __syncthreads();

        float s[8][4];
        #pragma unroll
        for (int nt = 0; nt < 8; nt++)
            #pragma unroll
            for (int q = 0; q < 4; q++) s[nt][q] = 0.f;

        #pragma unroll
        for (int kk = 0; kk < 8; kk++) {
            #pragma unroll
            for (int nt = 0; nt < 8; nt++) {
                int kb = (nt * 8 + g) * KST + kk * 8 + tg;
                uint32_t b0 = Ku[kb];
                uint32_t b1 = Ku[kb + 4];
                mma_tf32(s[nt][0], s[nt][1], s[nt][2], s[nt][3],
                         qa[kk][0], qa[kk][1], qa[kk][2], qa[kk][3], b0, b1);
            }
        }

        if (kt == qt) {
            int i0 = w * 16 + g, i1 = i0 + 8;
            #pragma unroll
            for (int nt = 0; nt < 8; nt++) {
                int j0 = nt * 8 + 2 * tg;
                if (j0     > i0) s[nt][0] = NEG_INF;
                if (j0 + 1 > i0) s[nt][1] = NEG_INF;
                if (j0     > i1) s[nt][2] = NEG_INF;
                if (j0 + 1 > i1) s[nt][3] = NEG_INF;
            }
        }

        float r0 = NEG_INF, r1 = NEG_INF;
        #pragma unroll
        for (int nt = 0; nt < 8; nt++) {
            r0 = fmaxf(r0, fmaxf(s[nt][0], s[nt][1]));
            r1 = fmaxf(r1, fmaxf(s[nt][2], s[nt][3]));
        }
        r0 = fmaxf(r0, __shfl_xor_sync(0xffffffffu, r0, 1));
        r0 = fmaxf(r0, __shfl_xor_sync(0xffffffffu, r0, 2));
        r1 = fmaxf(r1, __shfl_xor_sync(0xffffffffu, r1, 1));
        r1 = fmaxf(r1, __shfl_xor_sync(0xffffffffu, r1, 2));

        float nm0 = fmaxf(m0, r0), nm1 = fmaxf(m1, r1);
        float a0 = __expf(m0 - nm0), a1 = __expf(m1 - nm1);
        float sum0 = 0.f, sum1 = 0.f;
        #pragma unroll
        for (int nt = 0; nt < 8; nt++) {
            s[nt][0] = __expf(s[nt][0] - nm0);
            s[nt][1] = __expf(s[nt][1] - nm0);
            s[nt][2] = __expf(s[nt][2] - nm1);
            s[nt][3] = __expf(s[nt][3] - nm1);
            sum0 += s[nt][0] + s[nt][1];
            sum1 += s[nt][2] + s[nt][3];
        }
        sum0 += __shfl_xor_sync(0xffffffffu, sum0, 1);
        sum0 += __shfl_xor_sync(0xffffffffu, sum0, 2);
        sum1 += __shfl_xor_sync(0xffffffffu, sum1, 1);
        sum1 += __shfl_xor_sync(0xffffffffu, sum1, 2);
        m0 = nm0; m1 = nm1;
        l0 = l0 * a0 + sum0;
        l1 = l1 * a1 + sum1;

        #pragma unroll
        for (int nt = 0; nt < 8; nt++) {
            o[nt][0] *= a0; o[nt][1] *= a0;
            o[nt][2] *= a1; o[nt][3] *= a1;
        }

        #pragma unroll
        for (int nt = 0; nt < 8; nt++) {
            int c0 = nt * 8 + 2 * tg;
            Pu[pr0 + c0]     = f2tf32(s[nt][0]);
            Pu[pr0 + c0 + 1] = f2tf32(s[nt][1]);
            Pu[pr1 + c0]     = f2tf32(s[nt][2]);
            Pu[pr1 + c0 + 1] = f2tf32(s[nt][3]);
        }
        __syncwarp();

        #pragma unroll
        for (int kk = 0; kk < 8; kk++) {
            uint32_t pa0 = Pu[pr0 + kk * 8 + tg];
            uint32_t pa1 = Pu[pr1 + kk * 8 + tg];
            uint32_t pa2 = Pu[pr0 + kk * 8 + tg + 4];
            uint32_t pa3 = Pu[pr1 + kk * 8 + tg + 4];
            #pragma unroll
            for (int nt = 0; nt < 8; nt++) {
                uint32_t b0 = Vu[(kk * 8 + tg) * VST + nt * 8 + g];
                uint32_t b1 = Vu[(kk * 8 + tg + 4) * VST + nt * 8 + g];
                mma_tf32(o[nt][0], o[nt][1], o[nt][2], o[nt][3],
                         pa0, pa1, pa2, pa3, b0, b1);
            }
        }
    }

    // Epilogue: scale by 1/l, tf32-round, write K-PERMUTED for the proj GEMM.
    // Column c within its 8-block goes to position 2*(c&3) + (c>>2).
    float i0v = 1.f / l0, i1v = 1.f / l1;
    const int c0l = 2 * tg, c1l = 2 * tg + 1;
    const int p0 = 2 * (c0l & 3) + (c0l >> 2);
    const int p1 = 2 * (c1l & 3) + (c1l >> 2);
    uint32_t* o0p = (uint32_t*)(out + (size_t)(b * Sz + q0 + w * 16 + g) * Dz + h * HDz);
    uint32_t* o1p = o0p + (size_t)8 * Dz;
    #pragma unroll
    for (int nt = 0; nt < 8; nt++) {
        o0p[nt * 8 + p0] = f2tf32(o[nt][0] * i0v);
        o0p[nt * 8 + p1] = f2tf32(o[nt][1] * i0v);
        o1p[nt * 8 + p0] = f2tf32(o[nt][2] * i1v);
        o1p[nt * 8 + p1] = f2tf32(o[nt][3] * i1v);
    }
}

// ---------------------------------------------------------------------------
extern "C" void kernel_launch(void* const* d_in, const int* in_sizes, int n_in,
                              void* d_out, int out_size)
{
    const float* x      = (const float*)d_in[0];
    const float* w_qkv  = (const float*)d_in[1];
    const float* w_proj = (const float*)d_in[2];
    float* out = (float*)d_out;

    void *qkvp, *attnp, *xp, *wqp, *wpp;
    cudaGetSymbolAddress(&qkvp, g_qkv);
    cudaGetSymbolAddress(&attnp, g_attn);
    cudaGetSymbolAddress(&xp, g_x);
    cudaGetSymbolAddress(&wqp, g_wq);
    cudaGetSymbolAddress(&wpp, g_wp);

    cudaFuncSetAttribute(attn_mma_kernel,
                         cudaFuncAttributeMaxDynamicSharedMemorySize, ATT_SMEM);
    cudaFuncSetAttribute(gemm_mma_kernel,
                         cudaFuncAttributeMaxDynamicSharedMemorySize, GEMM_SMEM);

    const int M = Mz;

    // 0) tf32-round + K-permute all GEMM inputs in one pass
    {
        int total = N8_X + N8_WQ + N8_WP;
        cvt_all_kernel<<<(total + 255) / 256, 256>>>(
            x, (float*)xp, w_qkv, (float*)wqp, w_proj, (float*)wpp);
    }

    // 1) QKV projection (tensor cores): [8192,1024] x [3072,1024]^T
    gemm_mma_kernel<<<dim3(D3z / 128, M / 128), 256, GEMM_SMEM>>>(
        (const float*)xp, (const float*)wqp, (float*)qkvp, M, D3z, Dz);

    // 2) Causal flash attention (tensor cores) -> g_attn (tf32, K-permuted)
    attn_mma_kernel<<<dim3(Sz / 64, Hz, Bz), 128, ATT_SMEM>>>(
        (const float*)qkvp, (float*)attnp);

    // 3) Output projection (tensor cores): [8192,1024] x [1024,1024]^T
    gemm_mma_kernel<<<dim3(Dz / 128, M / 128), 256, GEMM_SMEM>>>(
        (const float*)attnp, (const float*)wpp, out, M, Dz, Dz);
}

// round 9
// speedup vs baseline: 1.5114x; 1.4784x over previous
#include <cuda_runtime.h>
#include <cuda_fp16.h>
#include <cstdint>
#include <math.h>

// Problem constants
#define Bz 4
#define Sz 2048
#define Dz 1024
#define Hz 16
#define HDz 64
#define D3z 3072
#define Mz (Bz * Sz)

// Scratch (device globals: allocation-free per harness rules)
// fp16 buffers are K-pair-permuted: within each 16-element K-block, half2
// pairs are ordered [m0,m4,m1,m5,m2,m6,m3,m7] (m = pair (2m,2m+1)).
__device__ float    g_qkv[(size_t)Mz * D3z];      // [8192,3072] fp32
__device__ uint32_t g_attn[(size_t)Mz * Dz / 2];  // fp16, permuted
__device__ uint32_t g_x  [(size_t)Mz * Dz / 2];   // fp16, permuted
__device__ uint32_t g_wq [(size_t)D3z * Dz / 2];  // fp16, permuted
__device__ uint32_t g_wp [(size_t)Dz * Dz / 2];   // fp16, permuted

// ---------------------------------------------------------------------------
// Helpers
// ---------------------------------------------------------------------------
__device__ __forceinline__ uint32_t smem_u32(const void* p) {
    uint32_t a;
    asm("{ .reg .u64 t; cvta.to.shared.u64 t, %1; cvt.u32.u64 %0, t; }"
        : "=r"(a) : "l"(p));
    return a;
}

__device__ __forceinline__ uint32_t f2tf32(float x) {
    uint32_t r;
    asm("cvt.rna.tf32.f32 %0, %1;" : "=r"(r) : "f"(x));
    return r;
}

__device__ __forceinline__ uint32_t f2h2(float a, float b) {
    __half2 h = __floats2half2_rn(a, b);   // low 16 bits = a
    return *(uint32_t*)&h;
}

#define CP_ASYNC16(dst, src) \
    asm volatile("cp.async.cg.shared.global [%0], [%1], 16;" \
        :: "r"((uint32_t)(dst)), "l"(src) : "memory")
#define CP_COMMIT() asm volatile("cp.async.commit_group;" ::: "memory")
#define CP_WAIT1() asm volatile("cp.async.wait_group 1;" ::: "memory")
#define CP_WAIT0() asm volatile("cp.async.wait_group 0;" ::: "memory")

// m16n8k16 fp16 MMA, fp32 accumulate (sm_80+, valid at compute_103)
__device__ __forceinline__ void mma_f16(
    float& d0, float& d1, float& d2, float& d3,
    uint32_t a0, uint32_t a1, uint32_t a2, uint32_t a3,
    uint32_t b0, uint32_t b1)
{
    asm volatile(
        "mma.sync.aligned.m16n8k16.row.col.f32.f16.f16.f32 "
        "{%0,%1,%2,%3}, {%4,%5,%6,%7}, {%8,%9}, {%0,%1,%2,%3};"
        : "+f"(d0), "+f"(d1), "+f"(d2), "+f"(d3)
        : "r"(a0), "r"(a1), "r"(a2), "r"(a3), "r"(b0), "r"(b1));
}

// m16n8k8 tf32 MMA (for attention PV)
__device__ __forceinline__ void mma_tf32(
    float& d0, float& d1, float& d2, float& d3,
    uint32_t a0, uint32_t a1, uint32_t a2, uint32_t a3,
    uint32_t b0, uint32_t b1)
{
    asm volatile(
        "mma.sync.aligned.m16n8k8.row.col.f32.tf32.tf32.f32 "
        "{%0,%1,%2,%3}, {%4,%5,%6,%7}, {%8,%9}, {%0,%1,%2,%3};"
        : "+f"(d0), "+f"(d1), "+f"(d2), "+f"(d3)
        : "r"(a0), "r"(a1), "r"(a2), "r"(a3), "r"(b0), "r"(b1));
}

// ---------------------------------------------------------------------------
// Fused fp16 conversion + K-pair permute over x, w_qkv, w_proj.
// Thread handles one 16-float K-block -> 8 half2 in order [0,4,1,5,2,6,3,7].
// ---------------------------------------------------------------------------
#define N16_X  (Mz * Dz / 16)
#define N16_WQ (D3z * Dz / 16)
#define N16_WP (Dz * Dz / 16)

__global__ __launch_bounds__(256) void cvt_all_kernel(
    const float* __restrict__ x,  uint32_t* __restrict__ xo,
    const float* __restrict__ wq, uint32_t* __restrict__ wqo,
    const float* __restrict__ wp, uint32_t* __restrict__ wpo)
{
    int i = blockIdx.x * blockDim.x + threadIdx.x;
    const float4* src;
    uint4* dst;
    int j;
    if (i < N16_X)                { src = (const float4*)x;  dst = (uint4*)xo;  j = i; }
    else if (i < N16_X + N16_WQ)  { src = (const float4*)wq; dst = (uint4*)wqo; j = i - N16_X; }
    else if (i < N16_X + N16_WQ + N16_WP)
                                  { src = (const float4*)wp; dst = (uint4*)wpo; j = i - N16_X - N16_WQ; }
    else return;
    float4 v0 = src[4 * j], v1 = src[4 * j + 1];
    float4 v2 = src[4 * j + 2], v3 = src[4 * j + 3];
    uint32_t m0 = f2h2(v0.x, v0.y), m1 = f2h2(v0.z, v0.w);
    uint32_t m2 = f2h2(v1.x, v1.y), m3 = f2h2(v1.z, v1.w);
    uint32_t m4 = f2h2(v2.x, v2.y), m5 = f2h2(v2.z, v2.w);
    uint32_t m6 = f2h2(v3.x, v3.y), m7 = f2h2(v3.z, v3.w);
    dst[2 * j]     = make_uint4(m0, m4, m1, m5);
    dst[2 * j + 1] = make_uint4(m2, m6, m3, m7);
}

// ---------------------------------------------------------------------------
// fp16 mma.sync NT GEMM on permuted fp16 inputs. C fp32.
// 128x128 CTA, BK=32 halves, 8 warps (4Mx2N). 3-stage cp.async,
// row stride 24 uint32 (conflict-free LDS.64 frags). 2 CTAs/SM.
// K is given in HALVES.
// ---------------------------------------------------------------------------
#define STAGES 3
#define BKH 32
#define AST32 24
#define STAGE_U32 (128 * AST32 * 2)            // 6144 uint32
#define GEMM_SMEM (STAGES * STAGE_U32 * 4)     // 73728 bytes

__global__ __launch_bounds__(256, 2)
void gemm_mma_kernel(const uint32_t* __restrict__ A, const uint32_t* __restrict__ B,
                     float* __restrict__ C, int M, int N, int K)
{
    extern __shared__ uint32_t smu[];
    uint32_t sb = smem_u32(smu);
    const int tid = threadIdx.x;
    const int wid = tid >> 5;
    const int l   = tid & 31;
    const int g   = l >> 2;
    const int tg  = l & 3;
    const int wm  = wid >> 1;
    const int wn  = wid & 1;
    const int m0  = blockIdx.y * 128;
    const int n0  = blockIdx.x * 128;
    const int nchunk = K / BKH;
    const int rs  = K / 2;              // uint32 per gmem row

    auto issue = [&](int c, int s) {
        uint32_t sA = sb + (uint32_t)s * STAGE_U32 * 4;
        uint32_t sB = sA + 128u * AST32 * 4;
        const uint32_t* Ab = A + (size_t)m0 * rs + c * (BKH / 2);
        const uint32_t* Bb = B + (size_t)n0 * rs + c * (BKH / 2);
        #pragma unroll
        for (int i = 0; i < 2; i++) {
            int idx = tid + 256 * i;        // 0..511
            int row = idx >> 2;
            int c4  = idx & 3;
            uint32_t so = (uint32_t)(row * AST32 + c4 * 4) * 4;
            CP_ASYNC16(sA + so, Ab + (size_t)row * rs + c4 * 4);
            CP_ASYNC16(sB + so, Bb + (size_t)row * rs + c4 * 4);
        }
        CP_COMMIT();
    };

    float acc[2][8][4];
    #pragma unroll
    for (int mt = 0; mt < 2; mt++)
        #pragma unroll
        for (int nt = 0; nt < 8; nt++)
            #pragma unroll
            for (int q = 0; q < 4; q++) acc[mt][nt][q] = 0.f;

    issue(0, 0);
    issue(1, 1);

    const int abase = (wm * 32 + g) * AST32 + 2 * tg;   // +mt*16*AST32 +s*8
    const int bbase = (wn * 64 + g) * AST32 + 2 * tg;   // +nt*8*AST32 +s*8

    for (int c = 0; c < nchunk; c++) {
        if (c == nchunk - 1) { CP_WAIT0(); } else { CP_WAIT1(); }
        __syncthreads();

        int cn = c + 2;
        if (cn < nchunk) issue(cn, cn % STAGES);

        const uint32_t* Au = smu + (size_t)(c % STAGES) * STAGE_U32;
        const uint32_t* Bu = Au + 128 * AST32;

        #pragma unroll
        for (int s = 0; s < 2; s++) {       // two k16-steps per chunk
            uint32_t a[2][4];
            #pragma unroll
            for (int mt = 0; mt < 2; mt++) {
                uint2 lo = *(const uint2*)&Au[abase + mt * 16 * AST32 + s * 8];            // (a0,a2)
                uint2 hi = *(const uint2*)&Au[abase + mt * 16 * AST32 + 8 * AST32 + s * 8]; // (a1,a3)
                a[mt][0] = lo.x; a[mt][2] = lo.y;
                a[mt][1] = hi.x; a[mt][3] = hi.y;
            }
            uint32_t b[8][2];
            #pragma unroll
            for (int nt = 0; nt < 8; nt++) {
                uint2 bv = *(const uint2*)&Bu[bbase + nt * 8 * AST32 + s * 8];             // (b0,b1)
                b[nt][0] = bv.x; b[nt][1] = bv.y;
            }
            #pragma unroll
            for (int mt = 0; mt < 2; mt++)
                #pragma unroll
                for (int nt = 0; nt < 8; nt++)
                    mma_f16(acc[mt][nt][0], acc[mt][nt][1],
                            acc[mt][nt][2], acc[mt][nt][3],
                            a[mt][0], a[mt][1], a[mt][2], a[mt][3],
                            b[nt][0], b[nt][1]);
        }
    }

    #pragma unroll
    for (int mt = 0; mt < 2; mt++) {
        int r = m0 + wm * 32 + mt * 16 + g;
        #pragma unroll
        for (int nt = 0; nt < 8; nt++) {
            int cc = n0 + wn * 64 + nt * 8 + tg * 2;
            *(float2*)&C[(size_t)r * N + cc] =
                make_float2(acc[mt][nt][0], acc[mt][nt][1]);
            *(float2*)&C[(size_t)(r + 8) * N + cc] =
                make_float2(acc[mt][nt][2], acc[mt][nt][3]);
        }
    }
}

// ---------------------------------------------------------------------------
// Flash attention: QK^T in fp16 (m16n8k16), PV in tf32 (m16n8k8).
// QTILE=64, 4 CTAs/SM. Longest CTAs first. Epilogue: permuted fp16.
// ---------------------------------------------------------------------------
#define KST32 36     // K tile: 64 rows x 32 uint32 (half2), stride 36
#define VST 72       // V tile: fp32/tf32, stride 72
#define PST 68       // P/Q staging: stride 68 uint32
#define ATT_U32 (64 * KST32 + 64 * VST + 64 * PST)
#define ATT_SMEM (ATT_U32 * 4)     // 45056 bytes

__global__ __launch_bounds__(128, 4) void attn_mma_kernel(
    const float* __restrict__ qkv, uint32_t* __restrict__ out)
{
    extern __shared__ uint32_t smu[];
    uint32_t* Kh = smu;
    uint32_t* Vu = smu + 64 * KST32;
    uint32_t* Pu = Vu + 64 * VST;

    const int tid = threadIdx.x;
    const int w  = tid >> 5;
    const int l  = tid & 31;
    const int g  = l >> 2;
    const int tg = l & 3;
    const int qt = gridDim.x - 1 - blockIdx.x;   // longest work first
    const int h  = blockIdx.y;
    const int b  = blockIdx.z;
    const int q0 = qt * 64;
    const size_t bh = (size_t)b * Sz * D3z + (size_t)h * HDz;
    const float NEG_INF = -__int_as_float(0x7f800000);

    // Stage Q (scaled by 1/8) as fp16 half2 into Pu rows (stride PST)
    for (int idx = tid; idx < 1024; idx += 128) {
        int r = idx >> 4, cf = (idx & 15) << 2;
        float4 v = *(const float4*)(qkv + bh + (size_t)(q0 + r) * D3z + cf);
        Pu[r * PST + (idx & 15) * 2]     = f2h2(v.x * 0.125f, v.y * 0.125f);
        Pu[r * PST + (idx & 15) * 2 + 1] = f2h2(v.z * 0.125f, v.w * 0.125f);
    }
    __syncthreads();

    // Q fragments for 4 k16-steps (fp16 m16n8k16 A-layout)
    uint32_t qa[4][4];
    const int pr0 = (w * 16 + g) * PST;
    const int pr1 = pr0 + 8 * PST;
    #pragma unroll
    for (int s = 0; s < 4; s++) {
        qa[s][0] = Pu[pr0 + s * 8 + tg];
        qa[s][1] = Pu[pr1 + s * 8 + tg];
        qa[s][2] = Pu[pr0 + s * 8 + tg + 4];
        qa[s][3] = Pu[pr1 + s * 8 + tg + 4];
    }

    float o[8][4];
    #pragma unroll
    for (int nt = 0; nt < 8; nt++)
        #pragma unroll
        for (int q = 0; q < 4; q++) o[nt][q] = 0.f;
    float m0 = NEG_INF, m1 = NEG_INF, l0 = 0.f, l1 = 0.f;

    for (int kt = 0; kt <= qt; kt++) {
        const int k0 = kt * 64;
        __syncthreads();
        for (int idx = tid; idx < 1024; idx += 128) {
            int r = idx >> 4, cf = (idx & 15) << 2;
            const float* p = qkv + bh + (size_t)(k0 + r) * D3z + Dz + cf;
            float4 kv = *(const float4*)p;
            float4 vv = *(const float4*)(p + Dz);
            Kh[r * KST32 + (idx & 15) * 2]     = f2h2(kv.x, kv.y);
            Kh[r * KST32 + (idx & 15) * 2 + 1] = f2h2(kv.z, kv.w);
            uint4 v4;
            v4.x = f2tf32(vv.x); v4.y = f2tf32(vv.y);
            v4.z = f2tf32(vv.z); v4.w = f2tf32(vv.w);
            *(uint4*)&Vu[r * VST + cf] = v4;
        }
        __syncthreads();

        // Scores S = Q K^T via fp16 m16n8k16 (4 k-steps)
        float s[8][4];
        #pragma unroll
        for (int nt = 0; nt < 8; nt++)
            #pragma unroll
            for (int q = 0; q < 4; q++) s[nt][q] = 0.f;

        #pragma unroll
        for (int ks = 0; ks < 4; ks++) {
            #pragma unroll
            for (int nt = 0; nt < 8; nt++) {
                int kb = (nt * 8 + g) * KST32 + ks * 8 + tg;
                uint32_t b0 = Kh[kb];
                uint32_t b1 = Kh[kb + 4];
                mma_f16(s[nt][0], s[nt][1], s[nt][2], s[nt][3],
                        qa[ks][0], qa[ks][1], qa[ks][2], qa[ks][3], b0, b1);
            }
        }

        if (kt == qt) {
            int i0 = w * 16 + g, i1 = i0 + 8;
            #pragma unroll
            for (int nt = 0; nt < 8; nt++) {
                int j0 = nt * 8 + 2 * tg;
                if (j0     > i0) s[nt][0] = NEG_INF;
                if (j0 + 1 > i0) s[nt][1] = NEG_INF;
                if (j0     > i1) s[nt][2] = NEG_INF;
                if (j0 + 1 > i1) s[nt][3] = NEG_INF;
            }
        }

        float r0 = NEG_INF, r1 = NEG_INF;
        #pragma unroll
        for (int nt = 0; nt < 8; nt++) {
            r0 = fmaxf(r0, fmaxf(s[nt][0], s[nt][1]));
            r1 = fmaxf(r1, fmaxf(s[nt][2], s[nt][3]));
        }
        r0 = fmaxf(r0, __shfl_xor_sync(0xffffffffu, r0, 1));
        r0 = fmaxf(r0, __shfl_xor_sync(0xffffffffu, r0, 2));
        r1 = fmaxf(r1, __shfl_xor_sync(0xffffffffu, r1, 1));
        r1 = fmaxf(r1, __shfl_xor_sync(0xffffffffu, r1, 2));

        float nm0 = fmaxf(m0, r0), nm1 = fmaxf(m1, r1);
        float a0 = __expf(m0 - nm0), a1 = __expf(m1 - nm1);
        float sum0 = 0.f, sum1 = 0.f;
        #pragma unroll
        for (int nt = 0; nt < 8; nt++) {
            s[nt][0] = __expf(s[nt][0] - nm0);
            s[nt][1] = __expf(s[nt][1] - nm0);
            s[nt][2] = __expf(s[nt][2] - nm1);
            s[nt][3] = __expf(s[nt][3] - nm1);
            sum0 += s[nt][0] + s[nt][1];
            sum1 += s[nt][2] + s[nt][3];
        }
        sum0 += __shfl_xor_sync(0xffffffffu, sum0, 1);
        sum0 += __shfl_xor_sync(0xffffffffu, sum0, 2);
        sum1 += __shfl_xor_sync(0xffffffffu, sum1, 1);
        sum1 += __shfl_xor_sync(0xffffffffu, sum1, 2);
        m0 = nm0; m1 = nm1;
        l0 = l0 * a0 + sum0;
        l1 = l1 * a1 + sum1;

        #pragma unroll
        for (int nt = 0; nt < 8; nt++) {
            o[nt][0] *= a0; o[nt][1] *= a0;
            o[nt][2] *= a1; o[nt][3] *= a1;
        }

        // P (tf32) to warp-private Pu rows
        #pragma unroll
        for (int nt = 0; nt < 8; nt++) {
            int c0 = nt * 8 + 2 * tg;
            Pu[pr0 + c0]     = f2tf32(s[nt][0]);
            Pu[pr0 + c0 + 1] = f2tf32(s[nt][1]);
            Pu[pr1 + c0]     = f2tf32(s[nt][2]);
            Pu[pr1 + c0 + 1] = f2tf32(s[nt][3]);
        }
        __syncwarp();

        // O += P V  (tf32 m16n8k8; V tf32 in Vu)
        #pragma unroll
        for (int kk = 0; kk < 8; kk++) {
            uint32_t pa0 = Pu[pr0 + kk * 8 + tg];
            uint32_t pa1 = Pu[pr1 + kk * 8 + tg];
            uint32_t pa2 = Pu[pr0 + kk * 8 + tg + 4];
            uint32_t pa3 = Pu[pr1 + kk * 8 + tg + 4];
            #pragma unroll
            for (int nt = 0; nt < 8; nt++) {
                uint32_t b0 = Vu[(kk * 8 + tg) * VST + nt * 8 + g];
                uint32_t b1 = Vu[(kk * 8 + tg + 4) * VST + nt * 8 + g];
                mma_tf32(o[nt][0], o[nt][1], o[nt][2], o[nt][3],
                         pa0, pa1, pa2, pa3, b0, b1);
            }
        }
    }

    // Epilogue: scale by 1/l, write K-pair-PERMUTED fp16 for the proj GEMM.
    // half2 pair index within 16-block: m=(nt&1)*4+tg -> slot (m<4)?2m:2(m-4)+1
    float i0v = 1.f / l0, i1v = 1.f / l1;
    uint32_t* o0p = out + ((size_t)(b * Sz + q0 + w * 16 + g) * Dz + h * HDz) / 2;
    uint32_t* o1p = o0p + (size_t)8 * Dz / 2;
    #pragma unroll
    for (int nt = 0; nt < 8; nt++) {
        int slot = (nt & 1) ? (2 * tg + 1) : (2 * tg);
        int oidx = (nt >> 1) * 8 + slot;
        o0p[oidx] = f2h2(o[nt][0] * i0v, o[nt][1] * i0v);
        o1p[oidx] = f2h2(o[nt][2] * i1v, o[nt][3] * i1v);
    }
}

// ---------------------------------------------------------------------------
extern "C" void kernel_launch(void* const* d_in, const int* in_sizes, int n_in,
                              void* d_out, int out_size)
{
    const float* x      = (const float*)d_in[0];
    const float* w_qkv  = (const float*)d_in[1];
    const float* w_proj = (const float*)d_in[2];
    float* out = (float*)d_out;

    void *qkvp, *attnp, *xp, *wqp, *wpp;
    cudaGetSymbolAddress(&qkvp, g_qkv);
    cudaGetSymbolAddress(&attnp, g_attn);
    cudaGetSymbolAddress(&xp, g_x);
    cudaGetSymbolAddress(&wqp, g_wq);
    cudaGetSymbolAddress(&wpp, g_wp);

    cudaFuncSetAttribute(attn_mma_kernel,
                         cudaFuncAttributeMaxDynamicSharedMemorySize, ATT_SMEM);
    cudaFuncSetAttribute(gemm_mma_kernel,
                         cudaFuncAttributeMaxDynamicSharedMemorySize, GEMM_SMEM);

    const int M = Mz;

    // 0) fp16-convert + K-pair-permute all GEMM inputs
    {
        int total = N16_X + N16_WQ + N16_WP;
        cvt_all_kernel<<<(total + 255) / 256, 256>>>(
            x, (uint32_t*)xp, w_qkv, (uint32_t*)wqp, w_proj, (uint32_t*)wpp);
    }

    // 1) QKV projection (fp16 tensor cores): [8192,1024] x [3072,1024]^T
    gemm_mma_kernel<<<dim3(D3z / 128, M / 128), 256, GEMM_SMEM>>>(
        (const uint32_t*)xp, (const uint32_t*)wqp, (float*)qkvp, M, D3z, Dz);

    // 2) Causal flash attention -> g_attn (fp16, permuted)
    attn_mma_kernel<<<dim3(Sz / 64, Hz, Bz), 128, ATT_SMEM>>>(
        (const float*)qkvp, (uint32_t*)attnp);

    // 3) Output projection (fp16 tensor cores): [8192,1024] x [1024,1024]^T
    gemm_mma_kernel<<<dim3(Dz / 128, M / 128), 256, GEMM_SMEM>>>(
        (const uint32_t*)attnp, (const uint32_t*)wpp, out, M, Dz, Dz);
}